// round 15
// baseline (speedup 1.0000x reference)
#include <cuda_runtime.h>
#include <cuda_fp16.h>
#include <cstdint>

#define N_ATOMS 4096
#define NG      12
#define N_GRID  1728
#define N_TOT   5824
#define HID     256
#define KNBR    32
#define NRBF    64
#define TAB     2048
#define NCAP    256
#define FCAP    768
#define CAP     1024
#define NCELL   6
#define NCELL3  216
#define CUTOFF  12.0f
#define BIGV    1e9f
#define NEAR2   36.0f

// ---------------- scratch (static __device__, no allocs) ----------------
__device__ float g_px[N_TOT], g_py[N_TOT], g_pz[N_TOT], g_ps[N_TOT];
__device__ int   g_zz[N_TOT];
__device__ unsigned char g_valid[N_TOT];
__device__ int   g_ginval[N_GRID];      // zero-init; finval reads then clears
__device__ int   g_cid[N_TOT];
__device__ int   g_ccnt[NCELL3];        // zero-init; re-zeroed each run by scan
__device__ int   g_cstart[NCELL3 + 1];
__device__ int   g_cfill[NCELL3];
__device__ float4 g_bpos[N_TOT];        // binned (x,y,z,ps)
__device__ int    g_bidx[N_TOT];        // binned node index
__device__ int   g_nbr[N_TOT * KNBR];
__device__ float g_dq[N_TOT * KNBR];
__device__ float g_E1[125 * HID];
__device__ __half2 g_E1h[125 * (HID / 2)];
__device__ float g_Wr1[NRBF * HID];
__device__ __half2 g_Th[TAB * HID];
__device__ float g_s[N_TOT * HID];
__device__ int   g_cnt[N_TOT];

// ---------------- packed f32x2 helpers ----------------------------------
__device__ __forceinline__ unsigned long long pk2(float lo, float hi) {
    unsigned long long r;
    asm("mov.b64 %0,{%1,%2};" : "=l"(r) : "f"(lo), "f"(hi));
    return r;
}
__device__ __forceinline__ void fma2(unsigned long long& d,
                                     unsigned long long a, unsigned long long b) {
    asm("fma.rn.f32x2 %0,%1,%2,%0;" : "+l"(d) : "l"(a), "l"(b));
}
__device__ __forceinline__ unsigned long long fma2o(unsigned long long a,
                                                    unsigned long long b,
                                                    unsigned long long c) {
    unsigned long long d;
    asm("fma.rn.f32x2 %0,%1,%2,%3;" : "=l"(d) : "l"(a), "l"(b), "l"(c));
    return d;
}
__device__ __forceinline__ unsigned long long add2(unsigned long long a,
                                                   unsigned long long b) {
    unsigned long long d;
    asm("add.rn.f32x2 %0,%1,%2;" : "=l"(d) : "l"(a), "l"(b));
    return d;
}
__device__ __forceinline__ unsigned long long mul2(unsigned long long a,
                                                   unsigned long long b) {
    unsigned long long d;
    asm("mul.rn.f32x2 %0,%1,%2;" : "=l"(d) : "l"(a), "l"(b));
    return d;
}
__device__ __forceinline__ float2 up2(unsigned long long v) {
    float2 f;
    asm("mov.b64 {%0,%1},%2;" : "=f"(f.x), "=f"(f.y) : "l"(v));
    return f;
}

// ---------------- K1: positions / z / norms / cell counts / repulsion ---
__global__ void k_setup(const float* __restrict__ pos,
                        const int* __restrict__ anum,
                        const float* __restrict__ cell) {
    int i = blockIdx.x * blockDim.x + threadIdx.x;
    if (i >= N_TOT) return;
    float x, y, z; int zz; unsigned char v;
    if (i < N_ATOMS) {
        x = pos[i * 3 + 0]; y = pos[i * 3 + 1]; z = pos[i * 3 + 2];
        zz = anum[i]; v = 1;
    } else {
        int g = i - N_ATOMS;
        int ia = g / (NG * NG), ib = (g / NG) % NG, ic = g % NG;
        float fa = (float)ia / NG, fb = (float)ib / NG, fc = (float)ic / NG;
        x = fa * cell[0] + fb * cell[3] + fc * cell[6];
        y = fa * cell[1] + fb * cell[4] + fc * cell[7];
        z = fa * cell[2] + fb * cell[5] + fc * cell[8];
        zz = 120; v = 0;
    }
    float ps = (x * x + y * y) + z * z;
    g_px[i] = x; g_py[i] = y; g_pz[i] = z;
    g_ps[i] = ps;
    g_zz[i] = zz; g_valid[i] = v;
    const float inv_cs = (float)NCELL / 40.0f;   // 0.15
    {
        int cx = min(max((int)(x * inv_cs), 0), NCELL - 1);
        int cy = min(max((int)(y * inv_cs), 0), NCELL - 1);
        int cz = min(max((int)(z * inv_cs), 0), NCELL - 1);
        int cid = (cx * NCELL + cy) * NCELL + cz;
        g_cid[i] = cid;
        atomicAdd(&g_ccnt[cid], 1);
    }
    // inverted repulsion: each atom invalidates grid nodes within 2A.
    // lattice spacing 40/12=3.33 > 2 so small index window per axis.
    if (i < N_ATOMS) {
        float hx = cell[0] / NG, hy = cell[4] / NG, hz = cell[8] / NG;
        int ia0 = max(0, (int)floorf((x - 2.0f) / hx));
        int ia1 = min(NG - 1, (int)ceilf((x + 2.0f) / hx));
        int ib0 = max(0, (int)floorf((y - 2.0f) / hy));
        int ib1 = min(NG - 1, (int)ceilf((y + 2.0f) / hy));
        int ic0 = max(0, (int)floorf((z - 2.0f) / hz));
        int ic1 = min(NG - 1, (int)ceilf((z + 2.0f) / hz));
        for (int ia = ia0; ia <= ia1; ia++)
        for (int ib = ib0; ib <= ib1; ib++)
        for (int ic = ic0; ic <= ic1; ic++) {
            float fa = (float)ia / NG, fb = (float)ib / NG, fc = (float)ic / NG;
            float nx = fa * cell[0] + fb * cell[3] + fc * cell[6];
            float ny = fa * cell[1] + fb * cell[4] + fc * cell[7];
            float nz = fa * cell[2] + fb * cell[5] + fc * cell[8];
            float psn = (nx * nx + ny * ny) + nz * nz;
            float d2 = psn + ps - 2.0f * ((nx * x + ny * y) + nz * z);
            if (d2 < 4.0f)
                atomicOr(&g_ginval[(ia * NG + ib) * NG + ic], 1);
        }
    }
}

// ---------------- K2b: finalize validity + parallel cell prefix scan ----
__global__ void k_finval() {
    if (blockIdx.x == 7) {
        __shared__ int sc[NCELL3];
        int t = threadIdx.x;
        int cnt = 0;
        if (t < NCELL3) { cnt = g_ccnt[t]; sc[t] = cnt; }
        __syncthreads();
        // Hillis-Steele inclusive scan over 216 entries
        #pragma unroll
        for (int off = 1; off < NCELL3; off <<= 1) {
            int v = 0;
            if (t < NCELL3 && t >= off) v = sc[t - off];
            __syncthreads();
            if (t < NCELL3) sc[t] += v;
            __syncthreads();
        }
        if (t < NCELL3) {
            int excl = sc[t] - cnt;
            g_cstart[t] = excl;
            g_cfill[t]  = excl;
            g_ccnt[t]   = 0;           // ready for next replay
        }
        if (t == 0) g_cstart[NCELL3] = N_TOT;
        return;
    }
    int gid = blockIdx.x * blockDim.x + threadIdx.x;
    if (gid >= N_GRID) return;
    bool bad = g_ginval[gid] != 0;
    g_ginval[gid] = 0;                                  // reset for next replay
    g_valid[N_ATOMS + gid] = bad ? 0 : 1;
    if (bad) g_ps[N_ATOMS + gid] += 3.0e9f;             // auto-fail cutoff
}

// ---------------- K2c: scatter nodes into cell bins ---------------------
__global__ void k_scatter() {
    int i = blockIdx.x * blockDim.x + threadIdx.x;
    if (i >= N_TOT) return;
    int cid = g_cid[i];
    int p = atomicAdd(&g_cfill[cid], 1);
    g_bpos[p] = make_float4(g_px[i], g_py[i], g_pz[i], g_ps[i]);
    g_bidx[p] = i;
}

// ---------------- K3: E1 = embed@W1 (+half2 copy), Wr1 = Wrbf@W1 --------
__global__ void __launch_bounds__(256) k_premm(const float* __restrict__ embed,
                                               const float* __restrict__ Wrbf,
                                               const float* __restrict__ W1) {
    __shared__ float srows[8 * HID];
    int r0 = blockIdx.x * 8;
    for (int idx = threadIdx.x; idx < 8 * HID; idx += 256) {
        int rr = idx >> 8, k = idx & 255;
        int row = r0 + rr;
        float v = 0.0f;
        if (row < 125) v = embed[row * HID + k];
        else if (row < 189) v = Wrbf[(row - 125) * HID + k];
        srows[idx] = v;
    }
    __syncthreads();
    int t = threadIdx.x;
    float acc[8];
    #pragma unroll
    for (int r = 0; r < 8; r++) acc[r] = 0.0f;
    #pragma unroll 8
    for (int k = 0; k < HID; k++) {
        float w = W1[k * HID + t];
        #pragma unroll
        for (int r = 0; r < 8; r++)
            acc[r] = fmaf(srows[r * HID + k], w, acc[r]);
    }
    #pragma unroll
    for (int r = 0; r < 8; r++) {
        int row = r0 + r;
        float hi = __shfl_down_sync(0xffffffffu, acc[r], 1);
        if (row < 125) {
            g_E1[row * HID + t] = acc[r];
            if ((t & 1) == 0)
                g_E1h[row * (HID / 2) + (t >> 1)] = __floats2half2_rn(acc[r], hi);
        } else if (row < 189) {
            g_Wr1[(row - 125) * HID + t] = acc[r];
        }
    }
}

// ---------------- K4: tabulate g(d)=rbf(d)@Wr1 -> half2 pairs -----------
#define TROWS 16
__global__ void __launch_bounds__(256) k_table() {
    __shared__ float rb[NRBF * TROWS];
    __shared__ float rbx[NRBF];
    int t = threadIdx.x;
    int row0 = blockIdx.x * TROWS;
    float wr[NRBF];
    #pragma unroll
    for (int j = 0; j < NRBF; j++) wr[j] = g_Wr1[j * HID + t];

    const float step = CUTOFF / (TAB - 1);
    const float inv_w = (float)NRBF / CUTOFF;
    #pragma unroll
    for (int p = 0; p < (NRBF * TROWS) / 256; p++) {
        int idx = t + 256 * p;
        int j = idx >> 4, r = idx & 15;
        float d = (float)(row0 + r) * step;
        float c = (float)j * (CUTOFF / (NRBF - 1));
        float u = (d - c) * inv_w;
        rb[idx] = __expf(-0.5f * u * u);
    }
    if (t < NRBF) {
        float d = (float)(row0 + TROWS) * step;
        float c = (float)t * (CUTOFF / (NRBF - 1));
        float u = (d - c) * inv_w;
        rbx[t] = __expf(-0.5f * u * u);
    }
    __syncthreads();

    float acc[TROWS + 1];
    #pragma unroll
    for (int r = 0; r <= TROWS; r++) acc[r] = 0.0f;
    #pragma unroll
    for (int j = 0; j < NRBF; j++) {
        float w = wr[j];
        const float4* rp = (const float4*)&rb[j * TROWS];
        #pragma unroll
        for (int g4 = 0; g4 < TROWS / 4; g4++) {
            float4 v = rp[g4];
            acc[g4 * 4 + 0] = fmaf(v.x, w, acc[g4 * 4 + 0]);
            acc[g4 * 4 + 1] = fmaf(v.y, w, acc[g4 * 4 + 1]);
            acc[g4 * 4 + 2] = fmaf(v.z, w, acc[g4 * 4 + 2]);
            acc[g4 * 4 + 3] = fmaf(v.w, w, acc[g4 * 4 + 3]);
        }
        acc[TROWS] = fmaf(rbx[j], w, acc[TROWS]);
    }
    #pragma unroll
    for (int r = 0; r < TROWS; r++)
        g_Th[(row0 + r) * HID + t] = __floats2half2_rn(acc[r], acc[r + 1]);
}

// ---------------- K5: top-K via cell list (near 3^3 + fallback 5^3) -----
__global__ void k_topk() {
    extern __shared__ unsigned long long lists[];   // 8 * CAP
    int warp = threadIdx.x >> 5, lane = threadIdx.x & 31;
    int row = blockIdx.x * 8 + warp;
    bool rv = g_valid[row] != 0;
    float xi = g_px[row], yi = g_py[row], zi = g_pz[row], si = g_ps[row];
    unsigned long long* list = lists + warp * CAP;
    unsigned lanemask_lt = (1u << lane) - 1u;
    int cid = g_cid[row];
    int cx = cid / (NCELL * NCELL), cy = (cid / NCELL) % NCELL, cz = cid % NCELL;
    int nc = 0, fc = 0;

    if (rv) {
        int x0 = max(cx - 1, 0), x1 = min(cx + 1, NCELL - 1);
        int y0 = max(cy - 1, 0), y1 = min(cy + 1, NCELL - 1);
        int z0 = max(cz - 1, 0), z1 = min(cz + 1, NCELL - 1);
        for (int dx = x0; dx <= x1; dx++)
        for (int dy = y0; dy <= y1; dy++)
        for (int dz = z0; dz <= z1; dz++) {
            int c = (dx * NCELL + dy) * NCELL + dz;
            int s0 = g_cstart[c], s1 = g_cstart[c + 1];
            for (int b = s0; b < s1; b += 32) {
                int idx = b + lane;
                bool nr = false; unsigned long long key = 0;
                if (idx < s1) {
                    float4 q = g_bpos[idx];
                    int j = g_bidx[idx];
                    float d2 = si + q.w - 2.0f * ((xi * q.x + yi * q.y) + zi * q.z);
                    if (d2 <= NEAR2 && j != row) {
                        nr = true;
                        key = ((unsigned long long)__float_as_uint(fmaxf(d2, 0.0f)) << 32)
                              | (unsigned)j;
                    }
                }
                unsigned mn = __ballot_sync(0xffffffffu, nr);
                if (nr) {
                    int p = nc + __popc(mn & lanemask_lt);
                    if (p < NCAP) list[p] = key;
                }
                nc += __popc(mn);
            }
        }
        if (nc < KNBR) {
            int fx0 = max(cx - 2, 0), fx1 = min(cx + 2, NCELL - 1);
            int fy0 = max(cy - 2, 0), fy1 = min(cy + 2, NCELL - 1);
            int fz0 = max(cz - 2, 0), fz1 = min(cz + 2, NCELL - 1);
            for (int dx = fx0; dx <= fx1; dx++)
            for (int dy = fy0; dy <= fy1; dy++)
            for (int dz = fz0; dz <= fz1; dz++) {
                int c = (dx * NCELL + dy) * NCELL + dz;
                int s0 = g_cstart[c], s1 = g_cstart[c + 1];
                for (int b = s0; b < s1; b += 32) {
                    int idx = b + lane;
                    bool fr = false; unsigned long long key = 0;
                    if (idx < s1) {
                        float4 q = g_bpos[idx];
                        int j = g_bidx[idx];
                        float d2 = si + q.w - 2.0f * ((xi * q.x + yi * q.y) + zi * q.z);
                        if (d2 > NEAR2 && d2 <= 145.0f) {
                            fr = true;
                            key = ((unsigned long long)__float_as_uint(d2) << 32)
                                  | (unsigned)j;
                        }
                    }
                    unsigned mf = __ballot_sync(0xffffffffu, fr);
                    if (fr) {
                        int p = fc + __popc(mf & lanemask_lt);
                        if (p < FCAP) list[NCAP + p] = key;
                    }
                    fc += __popc(mf);
                }
            }
        }
    }

    int len1 = 0, len2 = 0;
    if (rv) {
        len1 = min(nc, NCAP);
        len2 = (nc >= KNBR) ? 0 : min(fc, FCAP);
    }
    unsigned long long prev = 0;
    for (int e = 0; e < KNBR; e++) {
        unsigned long long best = ~0ull;
        for (int idx = lane; idx < len1; idx += 32) {
            unsigned long long v = list[idx];
            if (v > prev && v < best) best = v;
        }
        for (int idx = lane; idx < len2; idx += 32) {
            unsigned long long v = list[NCAP + idx];
            if (v > prev && v < best) best = v;
        }
        #pragma unroll
        for (int o = 16; o; o >>= 1) {
            unsigned long long ov = __shfl_down_sync(0xffffffffu, best, o);
            best = (ov < best) ? ov : best;
        }
        best = __shfl_sync(0xffffffffu, best, 0);
        if (lane == 0) {
            if (best == ~0ull) {
                g_nbr[row * KNBR + e] = 0;
                g_dq[row * KNBR + e] = BIGV;
            } else {
                float d2v = __uint_as_float((unsigned)(best >> 32));
                g_nbr[row * KNBR + e] = (int)(unsigned)(best & 0xffffffffu);
                g_dq[row * KNBR + e] = sqrtf(fmaxf(d2v, 1e-12f));
            }
        }
        prev = best;
    }
}

// ---------------- K6: per-edge z1 + silu (128 thr, f32x2 math) ----------
__global__ void __launch_bounds__(128) k_edges(const float* __restrict__ b1) {
    __shared__ float sf[KNBR];
    __shared__ int   si0[KNBR];
    __shared__ int   szo[KNBR];
    __shared__ int   sok[KNBR];
    int i = blockIdx.x, t = threadIdx.x;
    const float sc = (float)(TAB - 1) / CUTOFF;
    if (t < KNBR) {
        float d = g_dq[i * KNBR + t];
        bool ok = d <= CUTOFF;
        float u = d * sc;
        int i0 = min((int)u, TAB - 2);
        sf[t] = ok ? (u - (float)i0) : 0.0f;
        si0[t] = ok ? i0 * HID : 0;
        szo[t] = g_zz[g_nbr[i * KNBR + t]] * (HID / 2);
        sok[t] = ok ? 1 : 0;
        unsigned m = __ballot_sync(0xffffffffu, ok);
        if (t == 0) g_cnt[i] = __popc(m);
    }
    __syncthreads();

    int zi = g_zz[i];
    float2 e1 = *(const float2*)&g_E1[zi * HID + 2 * t];
    float2 bb = *(const float2*)&b1[2 * t];
    unsigned long long base2 = pk2(e1.x + bb.x, e1.y + bb.y);
    unsigned long long acc2  = pk2(0.0f, 0.0f);
    const unsigned long long c7 = pk2(-2.1081349e-4f, -2.1081349e-4f);
    const unsigned long long c5 = pk2( 2.0833333e-3f,  2.0833333e-3f);
    const unsigned long long c3 = pk2(-2.0833333e-2f, -2.0833333e-2f);
    const unsigned long long c1 = pk2( 2.5e-1f,        2.5e-1f);
    const unsigned long long ch = pk2( 5.0e-1f,        5.0e-1f);

    #pragma unroll 8
    for (int e = 0; e < KNBR; e++) {
        if (sok[e]) {
            float f = sf[e];
            __half2 pnh = g_E1h[szo[e] + t];
            uint2 thv = *(const uint2*)&g_Th[si0[e] + 2 * t];
            float2 pn = __half22float2(pnh);
            float2 gA = __half22float2(*(__half2*)&thv.x);
            float2 gB = __half22float2(*(__half2*)&thv.y);
            float g0 = fmaf(f, gA.y - gA.x, gA.x);
            float g1 = fmaf(f, gB.y - gB.x, gB.x);
            unsigned long long z = add2(add2(base2, pk2(pn.x, pn.y)), pk2(g0, g1));
            unsigned long long u = mul2(z, z);
            unsigned long long p = fma2o(c7, u, c5);
            p = fma2o(p, u, c3);
            p = fma2o(p, u, c1);
            unsigned long long sig = fma2o(z, p, ch);
            fma2(acc2, z, sig);     // acc += z * sigmoid(z)
        }
    }
    float2 accf = up2(acc2);
    *(float2*)&g_s[i * HID + 2 * t] = make_float2(accf.x, accf.y);
}

// ---------------- K7: feat = h + s@W2 + cnt*b2 (reg-tiled f32x2 GEMM) ---
#define FBM 64
#define FBN 128
#define FBK 32
__global__ void __launch_bounds__(256) k_final(const float* __restrict__ embed,
                                               const float* __restrict__ W2,
                                               const float* __restrict__ b2,
                                               float* __restrict__ out) {
    __shared__ float As[FBM * FBK];
    __shared__ float Bs[FBK * FBN];
    int tid = threadIdx.x;
    int tx = tid & 31;
    int ty = tid >> 5;
    int m0 = blockIdx.x * FBM;
    int n0 = blockIdx.y * FBN;

    unsigned long long acc[16];
    #pragma unroll
    for (int q = 0; q < 16; q++) acc[q] = 0ull;

    for (int k0 = 0; k0 < HID; k0 += FBK) {
        #pragma unroll
        for (int p = 0; p < (FBM * FBK) / 256; p++) {
            int idx = tid + 256 * p;
            int m = idx >> 5, k = idx & 31;
            As[idx] = g_s[(m0 + m) * HID + k0 + k];
        }
        #pragma unroll
        for (int p = 0; p < (FBK * FBN) / 256; p++) {
            int idx = tid + 256 * p;
            int kk = idx >> 7, n = idx & 127;
            Bs[idx] = W2[(k0 + kk) * HID + n0 + n];
        }
        __syncthreads();
        #pragma unroll
        for (int kk4 = 0; kk4 < FBK; kk4 += 4) {
            float4 a4[8];
            #pragma unroll
            for (int r = 0; r < 8; r++)
                a4[r] = *(const float4*)&As[(ty * 8 + r) * FBK + kk4];
            #pragma unroll
            for (int j = 0; j < 4; j++) {
                float4 bv = *(const float4*)&Bs[(kk4 + j) * FBN + tx * 4];
                unsigned long long b01 = pk2(bv.x, bv.y);
                unsigned long long b23 = pk2(bv.z, bv.w);
                #pragma unroll
                for (int r = 0; r < 8; r++) {
                    float a = (j == 0) ? a4[r].x : (j == 1) ? a4[r].y
                             : (j == 2) ? a4[r].z : a4[r].w;
                    unsigned long long aa = pk2(a, a);
                    fma2(acc[r * 2 + 0], aa, b01);
                    fma2(acc[r * 2 + 1], aa, b23);
                }
            }
        }
        __syncthreads();
    }

    int cbase = n0 + tx * 4;
    float4 b2v = *(const float4*)&b2[cbase];
    #pragma unroll
    for (int r = 0; r < 8; r++) {
        int node = m0 + ty * 8 + r;
        float2 p0 = up2(acc[r * 2 + 0]);
        float2 p1 = up2(acc[r * 2 + 1]);
        float4 res = make_float4(0.f, 0.f, 0.f, 0.f);
        if (g_valid[node]) {
            const float* em = embed + g_zz[node] * HID + cbase;
            float cf = (float)g_cnt[node];
            res.x = em[0] + p0.x + cf * b2v.x;
            res.y = em[1] + p0.y + cf * b2v.y;
            res.z = em[2] + p1.x + cf * b2v.z;
            res.w = em[3] + p1.y + cf * b2v.w;
        }
        *(float4*)&out[node * HID + cbase] = res;
    }

    if (blockIdx.y == 0 && tid < FBM) {
        int node = m0 + tid;
        float vn = (node >= N_ATOMS && g_valid[node]) ? 1.0f : 0.0f;
        float pn = (node < N_ATOMS) ? 1.0f : 0.0f;
        out[N_TOT * HID + node] = vn;
        out[N_TOT * HID + N_TOT + node] = pn;
    }
}

// ---------------- streams (created once at load, no device allocs) ------
struct StreamInit {
    cudaStream_t s2 = nullptr;
    cudaEvent_t evA = nullptr, evB = nullptr;
    bool ok = false;
    StreamInit() {
        ok = (cudaStreamCreateWithFlags(&s2, cudaStreamNonBlocking) == cudaSuccess)
          && (cudaEventCreateWithFlags(&evA, cudaEventDisableTiming) == cudaSuccess)
          && (cudaEventCreateWithFlags(&evB, cudaEventDisableTiming) == cudaSuccess);
    }
};
static StreamInit g_si;

// ---------------- launch -------------------------------------------------
extern "C" void kernel_launch(void* const* d_in, const int* in_sizes, int n_in,
                              void* d_out, int out_size) {
    const float* pos   = (const float*)d_in[0];
    const int*   anum  = (const int*)d_in[1];
    const float* cell  = (const float*)d_in[2];
    const float* embed = (const float*)d_in[3];
    const float* Wrbf  = (const float*)d_in[4];
    const float* W1    = (const float*)d_in[5];
    const float* b1    = (const float*)d_in[6];
    const float* W2    = (const float*)d_in[7];
    const float* b2    = (const float*)d_in[8];
    float* out = (float*)d_out;

    const int smem_topk = 8 * CAP * 8;   // 65536
    cudaFuncSetAttribute(k_topk, cudaFuncAttributeMaxDynamicSharedMemorySize, smem_topk);

    if (g_si.ok) {
        // fork: premm+table run on side stream, independent of topk chain
        cudaEventRecord(g_si.evA, 0);
        cudaStreamWaitEvent(g_si.s2, g_si.evA, 0);
        k_premm<<<(189 + 7) / 8, 256, 0, g_si.s2>>>(embed, Wrbf, W1);
        k_table<<<TAB / TROWS, 256, 0, g_si.s2>>>();
        cudaEventRecord(g_si.evB, g_si.s2);
    }

    k_setup<<<(N_TOT + 255) / 256, 256>>>(pos, anum, cell);
    k_finval<<<8, 256>>>();
    k_scatter<<<(N_TOT + 255) / 256, 256>>>();
    k_topk<<<N_TOT / 8, 256, smem_topk>>>();

    if (g_si.ok) {
        cudaStreamWaitEvent(0, g_si.evB, 0);   // join before edges
    } else {
        k_premm<<<(189 + 7) / 8, 256>>>(embed, Wrbf, W1);
        k_table<<<TAB / TROWS, 256>>>();
    }

    k_edges<<<N_TOT, 128>>>(b1);
    k_final<<<dim3(N_TOT / FBM, HID / FBN), 256>>>(embed, W2, b2, out);
}

// round 16
// speedup vs baseline: 1.0627x; 1.0627x over previous
#include <cuda_runtime.h>
#include <cuda_fp16.h>
#include <cstdint>

#define N_ATOMS 4096
#define NG      12
#define N_GRID  1728
#define N_TOT   5824
#define HID     256
#define KNBR    32
#define NRBF    64
#define TAB     2048
#define NCAP    256
#define FCAP    768
#define CAP     1024
#define NCELL   6
#define NCELL3  216
#define CAPB    96
#define CUTOFF  12.0f
#define BIGV    1e9f
#define NEAR2   36.0f

// ---------------- scratch (static __device__, no allocs) ----------------
__device__ float g_px[N_TOT], g_py[N_TOT], g_pz[N_TOT], g_ps[N_TOT];
__device__ int   g_zz[N_TOT];
__device__ unsigned char g_valid[N_TOT];
__device__ unsigned g_mind2u[N_GRID];
__device__ int   g_cid[N_TOT];
__device__ int   g_bcnt[NCELL3];        // zero-init; reset by k_edges each run
__device__ float4 g_bpos[NCELL3 * CAPB]; // fixed-stride bins (x,y,z,psAdj)
__device__ int    g_bidx[NCELL3 * CAPB];
__device__ int   g_nbr[N_TOT * KNBR];
__device__ float g_dq[N_TOT * KNBR];
__device__ float g_E1[125 * HID];
__device__ __half2 g_E1h[125 * (HID / 2)];
__device__ float g_Wr1[NRBF * HID];
__device__ __half2 g_Th[TAB * HID];
__device__ float g_s[N_TOT * HID];
__device__ int   g_cnt[N_TOT];

// ---------------- packed f32x2 helpers ----------------------------------
__device__ __forceinline__ unsigned long long pk2(float lo, float hi) {
    unsigned long long r;
    asm("mov.b64 %0,{%1,%2};" : "=l"(r) : "f"(lo), "f"(hi));
    return r;
}
__device__ __forceinline__ void fma2(unsigned long long& d,
                                     unsigned long long a, unsigned long long b) {
    asm("fma.rn.f32x2 %0,%1,%2,%0;" : "+l"(d) : "l"(a), "l"(b));
}
__device__ __forceinline__ unsigned long long fma2o(unsigned long long a,
                                                    unsigned long long b,
                                                    unsigned long long c) {
    unsigned long long d;
    asm("fma.rn.f32x2 %0,%1,%2,%3;" : "=l"(d) : "l"(a), "l"(b), "l"(c));
    return d;
}
__device__ __forceinline__ unsigned long long add2(unsigned long long a,
                                                   unsigned long long b) {
    unsigned long long d;
    asm("add.rn.f32x2 %0,%1,%2;" : "=l"(d) : "l"(a), "l"(b));
    return d;
}
__device__ __forceinline__ unsigned long long mul2(unsigned long long a,
                                                   unsigned long long b) {
    unsigned long long d;
    asm("mul.rn.f32x2 %0,%1,%2;" : "=l"(d) : "l"(a), "l"(b));
    return d;
}
__device__ __forceinline__ float2 up2(unsigned long long v) {
    float2 f;
    asm("mov.b64 {%0,%1},%2;" : "=f"(f.x), "=f"(f.y) : "l"(v));
    return f;
}

// ---------------- K1: positions / z / norms / cell id -------------------
__global__ void k_setup(const float* __restrict__ pos,
                        const int* __restrict__ anum,
                        const float* __restrict__ cell) {
    int i = blockIdx.x * blockDim.x + threadIdx.x;
    if (i >= N_TOT) return;
    if (i < N_GRID) g_mind2u[i] = 0x7F7FFFFFu;
    float x, y, z; int zz; unsigned char v;
    if (i < N_ATOMS) {
        x = pos[i * 3 + 0]; y = pos[i * 3 + 1]; z = pos[i * 3 + 2];
        zz = anum[i]; v = 1;
    } else {
        int g = i - N_ATOMS;
        int ia = g / (NG * NG), ib = (g / NG) % NG, ic = g % NG;
        float fa = (float)ia / NG, fb = (float)ib / NG, fc = (float)ic / NG;
        x = fa * cell[0] + fb * cell[3] + fc * cell[6];
        y = fa * cell[1] + fb * cell[4] + fc * cell[7];
        z = fa * cell[2] + fb * cell[5] + fc * cell[8];
        zz = 120; v = 0;
    }
    g_px[i] = x; g_py[i] = y; g_pz[i] = z;
    g_ps[i] = (x * x + y * y) + z * z;
    g_zz[i] = zz; g_valid[i] = v;
    const float inv_cs = (float)NCELL / 40.0f;   // 0.15
    int cx = min(max((int)(x * inv_cs), 0), NCELL - 1);
    int cy = min(max((int)(y * inv_cs), 0), NCELL - 1);
    int cz = min(max((int)(z * inv_cs), 0), NCELL - 1);
    g_cid[i] = (cx * NCELL + cy) * NCELL + cz;
}

// ---------------- K2: repulsion mask (atom-split, atomicMin) ------------
#define VSPLIT 32
#define VCHUNK (N_ATOMS / VSPLIT)   // 128
__global__ void k_vmask() {
    __shared__ float4 tile[VCHUNK];
    int node = blockIdx.x * blockDim.x + threadIdx.x;
    int a0 = blockIdx.y * VCHUNK;
    if (threadIdx.x < VCHUNK) {
        int a = a0 + threadIdx.x;
        tile[threadIdx.x] = make_float4(g_px[a], g_py[a], g_pz[a], g_ps[a]);
    }
    __syncthreads();
    if (node >= N_GRID) return;
    int i = N_ATOMS + node;
    float x = g_px[i], y = g_py[i], z = g_pz[i], s = g_ps[i];
    float mind2 = BIGV;
    #pragma unroll 8
    for (int e = 0; e < VCHUNK; e++) {
        float4 q = tile[e];
        float d2 = s + q.w - 2.0f * ((x * q.x + y * q.y) + z * q.z);
        mind2 = fminf(mind2, d2);
    }
    atomicMin(&g_mind2u[node], __float_as_uint(fmaxf(mind2, 0.0f)));
}

// ---------------- K2c: validity finalize + scatter into fixed bins ------
__global__ void k_scatter() {
    int i = blockIdx.x * blockDim.x + threadIdx.x;
    if (i >= N_TOT) return;
    float x = g_px[i], y = g_py[i], z = g_pz[i], ps = g_ps[i];
    bool valid;
    if (i < N_ATOMS) {
        valid = true;
    } else {
        valid = __uint_as_float(g_mind2u[i - N_ATOMS]) >= 4.0f;  // d>=2
        g_valid[i] = valid ? 1 : 0;
    }
    float psA = valid ? ps : (ps + 3.0e9f);   // invalid auto-fails cutoff
    int cid = g_cid[i];
    int p = atomicAdd(&g_bcnt[cid], 1);
    if (p < CAPB) {
        g_bpos[cid * CAPB + p] = make_float4(x, y, z, psA);
        g_bidx[cid * CAPB + p] = i;
    }
}

// ---------------- K3: E1 = embed@W1 (+half2 copy), Wr1 = Wrbf@W1 --------
__global__ void __launch_bounds__(256) k_premm(const float* __restrict__ embed,
                                               const float* __restrict__ Wrbf,
                                               const float* __restrict__ W1) {
    __shared__ float srows[8 * HID];
    int r0 = blockIdx.x * 8;
    for (int idx = threadIdx.x; idx < 8 * HID; idx += 256) {
        int rr = idx >> 8, k = idx & 255;
        int row = r0 + rr;
        float v = 0.0f;
        if (row < 125) v = embed[row * HID + k];
        else if (row < 189) v = Wrbf[(row - 125) * HID + k];
        srows[idx] = v;
    }
    __syncthreads();
    int t = threadIdx.x;
    float acc[8];
    #pragma unroll
    for (int r = 0; r < 8; r++) acc[r] = 0.0f;
    #pragma unroll 8
    for (int k = 0; k < HID; k++) {
        float w = W1[k * HID + t];
        #pragma unroll
        for (int r = 0; r < 8; r++)
            acc[r] = fmaf(srows[r * HID + k], w, acc[r]);
    }
    #pragma unroll
    for (int r = 0; r < 8; r++) {
        int row = r0 + r;
        float hi = __shfl_down_sync(0xffffffffu, acc[r], 1);
        if (row < 125) {
            g_E1[row * HID + t] = acc[r];
            if ((t & 1) == 0)
                g_E1h[row * (HID / 2) + (t >> 1)] = __floats2half2_rn(acc[r], hi);
        } else if (row < 189) {
            g_Wr1[(row - 125) * HID + t] = acc[r];
        }
    }
}

// ---------------- K4: tabulate g(d)=rbf(d)@Wr1 -> half2 pairs -----------
#define TROWS 16
__global__ void __launch_bounds__(256) k_table() {
    __shared__ float rb[NRBF * TROWS];
    __shared__ float rbx[NRBF];
    int t = threadIdx.x;
    int row0 = blockIdx.x * TROWS;
    float wr[NRBF];
    #pragma unroll
    for (int j = 0; j < NRBF; j++) wr[j] = g_Wr1[j * HID + t];

    const float step = CUTOFF / (TAB - 1);
    const float inv_w = (float)NRBF / CUTOFF;
    #pragma unroll
    for (int p = 0; p < (NRBF * TROWS) / 256; p++) {
        int idx = t + 256 * p;
        int j = idx >> 4, r = idx & 15;
        float d = (float)(row0 + r) * step;
        float c = (float)j * (CUTOFF / (NRBF - 1));
        float u = (d - c) * inv_w;
        rb[idx] = __expf(-0.5f * u * u);
    }
    if (t < NRBF) {
        float d = (float)(row0 + TROWS) * step;
        float c = (float)t * (CUTOFF / (NRBF - 1));
        float u = (d - c) * inv_w;
        rbx[t] = __expf(-0.5f * u * u);
    }
    __syncthreads();

    float acc[TROWS + 1];
    #pragma unroll
    for (int r = 0; r <= TROWS; r++) acc[r] = 0.0f;
    #pragma unroll
    for (int j = 0; j < NRBF; j++) {
        float w = wr[j];
        const float4* rp = (const float4*)&rb[j * TROWS];
        #pragma unroll
        for (int g4 = 0; g4 < TROWS / 4; g4++) {
            float4 v = rp[g4];
            acc[g4 * 4 + 0] = fmaf(v.x, w, acc[g4 * 4 + 0]);
            acc[g4 * 4 + 1] = fmaf(v.y, w, acc[g4 * 4 + 1]);
            acc[g4 * 4 + 2] = fmaf(v.z, w, acc[g4 * 4 + 2]);
            acc[g4 * 4 + 3] = fmaf(v.w, w, acc[g4 * 4 + 3]);
        }
        acc[TROWS] = fmaf(rbx[j], w, acc[TROWS]);
    }
    #pragma unroll
    for (int r = 0; r < TROWS; r++)
        g_Th[(row0 + r) * HID + t] = __floats2half2_rn(acc[r], acc[r + 1]);
}

// ---------------- K5: top-K via fixed-stride cell bins ------------------
__global__ void k_topk() {
    extern __shared__ unsigned long long lists[];   // 8 * CAP
    int warp = threadIdx.x >> 5, lane = threadIdx.x & 31;
    int row = blockIdx.x * 8 + warp;
    bool rv = g_valid[row] != 0;
    float xi = g_px[row], yi = g_py[row], zi = g_pz[row], si = g_ps[row];
    unsigned long long* list = lists + warp * CAP;
    unsigned lanemask_lt = (1u << lane) - 1u;
    int cid = g_cid[row];
    int cx = cid / (NCELL * NCELL), cy = (cid / NCELL) % NCELL, cz = cid % NCELL;
    int nc = 0, fc = 0;

    if (rv) {
        int x0 = max(cx - 1, 0), x1 = min(cx + 1, NCELL - 1);
        int y0 = max(cy - 1, 0), y1 = min(cy + 1, NCELL - 1);
        int z0 = max(cz - 1, 0), z1 = min(cz + 1, NCELL - 1);
        for (int dx = x0; dx <= x1; dx++)
        for (int dy = y0; dy <= y1; dy++)
        for (int dz = z0; dz <= z1; dz++) {
            int c = (dx * NCELL + dy) * NCELL + dz;
            int s0 = c * CAPB;
            int s1 = s0 + min(g_bcnt[c], CAPB);
            for (int b = s0; b < s1; b += 32) {
                int idx = b + lane;
                bool nr = false; unsigned long long key = 0;
                if (idx < s1) {
                    float4 q = g_bpos[idx];
                    int j = g_bidx[idx];
                    float d2 = si + q.w - 2.0f * ((xi * q.x + yi * q.y) + zi * q.z);
                    if (d2 <= NEAR2 && j != row) {
                        nr = true;
                        key = ((unsigned long long)__float_as_uint(fmaxf(d2, 0.0f)) << 32)
                              | (unsigned)j;
                    }
                }
                unsigned mn = __ballot_sync(0xffffffffu, nr);
                if (nr) {
                    int p = nc + __popc(mn & lanemask_lt);
                    if (p < NCAP) list[p] = key;
                }
                nc += __popc(mn);
            }
        }
        if (nc < KNBR) {
            int fx0 = max(cx - 2, 0), fx1 = min(cx + 2, NCELL - 1);
            int fy0 = max(cy - 2, 0), fy1 = min(cy + 2, NCELL - 1);
            int fz0 = max(cz - 2, 0), fz1 = min(cz + 2, NCELL - 1);
            for (int dx = fx0; dx <= fx1; dx++)
            for (int dy = fy0; dy <= fy1; dy++)
            for (int dz = fz0; dz <= fz1; dz++) {
                int c = (dx * NCELL + dy) * NCELL + dz;
                int s0 = c * CAPB;
                int s1 = s0 + min(g_bcnt[c], CAPB);
                for (int b = s0; b < s1; b += 32) {
                    int idx = b + lane;
                    bool fr = false; unsigned long long key = 0;
                    if (idx < s1) {
                        float4 q = g_bpos[idx];
                        int j = g_bidx[idx];
                        float d2 = si + q.w - 2.0f * ((xi * q.x + yi * q.y) + zi * q.z);
                        if (d2 > NEAR2 && d2 <= 145.0f) {
                            fr = true;
                            key = ((unsigned long long)__float_as_uint(d2) << 32)
                                  | (unsigned)j;
                        }
                    }
                    unsigned mf = __ballot_sync(0xffffffffu, fr);
                    if (fr) {
                        int p = fc + __popc(mf & lanemask_lt);
                        if (p < FCAP) list[NCAP + p] = key;
                    }
                    fc += __popc(mf);
                }
            }
        }
    }

    int len1 = 0, len2 = 0;
    if (rv) {
        len1 = min(nc, NCAP);
        len2 = (nc >= KNBR) ? 0 : min(fc, FCAP);
    }
    unsigned long long prev = 0;
    for (int e = 0; e < KNBR; e++) {
        unsigned long long best = ~0ull;
        for (int idx = lane; idx < len1; idx += 32) {
            unsigned long long v = list[idx];
            if (v > prev && v < best) best = v;
        }
        for (int idx = lane; idx < len2; idx += 32) {
            unsigned long long v = list[NCAP + idx];
            if (v > prev && v < best) best = v;
        }
        #pragma unroll
        for (int o = 16; o; o >>= 1) {
            unsigned long long ov = __shfl_down_sync(0xffffffffu, best, o);
            best = (ov < best) ? ov : best;
        }
        best = __shfl_sync(0xffffffffu, best, 0);
        if (lane == 0) {
            if (best == ~0ull) {
                g_nbr[row * KNBR + e] = 0;
                g_dq[row * KNBR + e] = BIGV;
            } else {
                float d2v = __uint_as_float((unsigned)(best >> 32));
                g_nbr[row * KNBR + e] = (int)(unsigned)(best & 0xffffffffu);
                g_dq[row * KNBR + e] = sqrtf(fmaxf(d2v, 1e-12f));
            }
        }
        prev = best;
    }
}

// ---------------- K6: per-edge z1 + silu (128 thr, f32x2 math) ----------
__global__ void __launch_bounds__(128) k_edges(const float* __restrict__ b1) {
    __shared__ float sf[KNBR];
    __shared__ int   si0[KNBR];
    __shared__ int   szo[KNBR];
    __shared__ int   sok[KNBR];
    int i = blockIdx.x, t = threadIdx.x;
    if (i < NCELL3 && t == 0) g_bcnt[i] = 0;   // reset bins for next replay
    const float sc = (float)(TAB - 1) / CUTOFF;
    if (t < KNBR) {
        float d = g_dq[i * KNBR + t];
        bool ok = d <= CUTOFF;
        float u = d * sc;
        int i0 = min((int)u, TAB - 2);
        sf[t] = ok ? (u - (float)i0) : 0.0f;
        si0[t] = ok ? i0 * HID : 0;
        szo[t] = g_zz[g_nbr[i * KNBR + t]] * (HID / 2);
        sok[t] = ok ? 1 : 0;
        unsigned m = __ballot_sync(0xffffffffu, ok);
        if (t == 0) g_cnt[i] = __popc(m);
    }
    __syncthreads();

    int zi = g_zz[i];
    float2 e1 = *(const float2*)&g_E1[zi * HID + 2 * t];
    float2 bb = *(const float2*)&b1[2 * t];
    unsigned long long base2 = pk2(e1.x + bb.x, e1.y + bb.y);
    unsigned long long acc2  = pk2(0.0f, 0.0f);
    const unsigned long long c7 = pk2(-2.1081349e-4f, -2.1081349e-4f);
    const unsigned long long c5 = pk2( 2.0833333e-3f,  2.0833333e-3f);
    const unsigned long long c3 = pk2(-2.0833333e-2f, -2.0833333e-2f);
    const unsigned long long c1 = pk2( 2.5e-1f,        2.5e-1f);
    const unsigned long long ch = pk2( 5.0e-1f,        5.0e-1f);

    #pragma unroll 8
    for (int e = 0; e < KNBR; e++) {
        if (sok[e]) {
            float f = sf[e];
            __half2 pnh = g_E1h[szo[e] + t];
            uint2 thv = *(const uint2*)&g_Th[si0[e] + 2 * t];
            float2 pn = __half22float2(pnh);
            float2 gA = __half22float2(*(__half2*)&thv.x);
            float2 gB = __half22float2(*(__half2*)&thv.y);
            float g0 = fmaf(f, gA.y - gA.x, gA.x);
            float g1 = fmaf(f, gB.y - gB.x, gB.x);
            unsigned long long z = add2(add2(base2, pk2(pn.x, pn.y)), pk2(g0, g1));
            unsigned long long u = mul2(z, z);
            unsigned long long p = fma2o(c7, u, c5);
            p = fma2o(p, u, c3);
            p = fma2o(p, u, c1);
            unsigned long long sig = fma2o(z, p, ch);
            fma2(acc2, z, sig);     // acc += z * sigmoid(z)
        }
    }
    float2 accf = up2(acc2);
    *(float2*)&g_s[i * HID + 2 * t] = make_float2(accf.x, accf.y);
}

// ---------------- K7: feat = h + s@W2 + cnt*b2 (reg-tiled f32x2 GEMM) ---
#define FBM 64
#define FBN 128
#define FBK 32
__global__ void __launch_bounds__(256) k_final(const float* __restrict__ embed,
                                               const float* __restrict__ W2,
                                               const float* __restrict__ b2,
                                               float* __restrict__ out) {
    __shared__ float As[FBM * FBK];
    __shared__ float Bs[FBK * FBN];
    int tid = threadIdx.x;
    int tx = tid & 31;
    int ty = tid >> 5;
    int m0 = blockIdx.x * FBM;
    int n0 = blockIdx.y * FBN;

    unsigned long long acc[16];
    #pragma unroll
    for (int q = 0; q < 16; q++) acc[q] = 0ull;

    for (int k0 = 0; k0 < HID; k0 += FBK) {
        #pragma unroll
        for (int p = 0; p < (FBM * FBK) / 256; p++) {
            int idx = tid + 256 * p;
            int m = idx >> 5, k = idx & 31;
            As[idx] = g_s[(m0 + m) * HID + k0 + k];
        }
        #pragma unroll
        for (int p = 0; p < (FBK * FBN) / 256; p++) {
            int idx = tid + 256 * p;
            int kk = idx >> 7, n = idx & 127;
            Bs[idx] = W2[(k0 + kk) * HID + n0 + n];
        }
        __syncthreads();
        #pragma unroll
        for (int kk4 = 0; kk4 < FBK; kk4 += 4) {
            float4 a4[8];
            #pragma unroll
            for (int r = 0; r < 8; r++)
                a4[r] = *(const float4*)&As[(ty * 8 + r) * FBK + kk4];
            #pragma unroll
            for (int j = 0; j < 4; j++) {
                float4 bv = *(const float4*)&Bs[(kk4 + j) * FBN + tx * 4];
                unsigned long long b01 = pk2(bv.x, bv.y);
                unsigned long long b23 = pk2(bv.z, bv.w);
                #pragma unroll
                for (int r = 0; r < 8; r++) {
                    float a = (j == 0) ? a4[r].x : (j == 1) ? a4[r].y
                             : (j == 2) ? a4[r].z : a4[r].w;
                    unsigned long long aa = pk2(a, a);
                    fma2(acc[r * 2 + 0], aa, b01);
                    fma2(acc[r * 2 + 1], aa, b23);
                }
            }
        }
        __syncthreads();
    }

    int cbase = n0 + tx * 4;
    float4 b2v = *(const float4*)&b2[cbase];
    #pragma unroll
    for (int r = 0; r < 8; r++) {
        int node = m0 + ty * 8 + r;
        float2 p0 = up2(acc[r * 2 + 0]);
        float2 p1 = up2(acc[r * 2 + 1]);
        float4 res = make_float4(0.f, 0.f, 0.f, 0.f);
        if (g_valid[node]) {
            const float* em = embed + g_zz[node] * HID + cbase;
            float cf = (float)g_cnt[node];
            res.x = em[0] + p0.x + cf * b2v.x;
            res.y = em[1] + p0.y + cf * b2v.y;
            res.z = em[2] + p1.x + cf * b2v.z;
            res.w = em[3] + p1.y + cf * b2v.w;
        }
        *(float4*)&out[node * HID + cbase] = res;
    }

    if (blockIdx.y == 0 && tid < FBM) {
        int node = m0 + tid;
        float vn = (node >= N_ATOMS && g_valid[node]) ? 1.0f : 0.0f;
        float pn = (node < N_ATOMS) ? 1.0f : 0.0f;
        out[N_TOT * HID + node] = vn;
        out[N_TOT * HID + N_TOT + node] = pn;
    }
}

// ---------------- streams (created once at load, no device allocs) ------
struct StreamInit {
    cudaStream_t s2 = nullptr;
    cudaEvent_t evA = nullptr, evB = nullptr;
    bool ok = false;
    StreamInit() {
        ok = (cudaStreamCreateWithFlags(&s2, cudaStreamNonBlocking) == cudaSuccess)
          && (cudaEventCreateWithFlags(&evA, cudaEventDisableTiming) == cudaSuccess)
          && (cudaEventCreateWithFlags(&evB, cudaEventDisableTiming) == cudaSuccess);
    }
};
static StreamInit g_si;

// ---------------- launch -------------------------------------------------
extern "C" void kernel_launch(void* const* d_in, const int* in_sizes, int n_in,
                              void* d_out, int out_size) {
    const float* pos   = (const float*)d_in[0];
    const int*   anum  = (const int*)d_in[1];
    const float* cell  = (const float*)d_in[2];
    const float* embed = (const float*)d_in[3];
    const float* Wrbf  = (const float*)d_in[4];
    const float* W1    = (const float*)d_in[5];
    const float* b1    = (const float*)d_in[6];
    const float* W2    = (const float*)d_in[7];
    const float* b2    = (const float*)d_in[8];
    float* out = (float*)d_out;

    const int smem_topk = 8 * CAP * 8;   // 65536
    cudaFuncSetAttribute(k_topk, cudaFuncAttributeMaxDynamicSharedMemorySize, smem_topk);

    if (g_si.ok) {
        // fork: premm+table run on side stream, independent of topk chain
        cudaEventRecord(g_si.evA, 0);
        cudaStreamWaitEvent(g_si.s2, g_si.evA, 0);
        k_premm<<<(189 + 7) / 8, 256, 0, g_si.s2>>>(embed, Wrbf, W1);
        k_table<<<TAB / TROWS, 256, 0, g_si.s2>>>();
        cudaEventRecord(g_si.evB, g_si.s2);
    }

    k_setup<<<(N_TOT + 255) / 256, 256>>>(pos, anum, cell);
    k_vmask<<<dim3((N_GRID + 255) / 256, VSPLIT), 256>>>();
    k_scatter<<<(N_TOT + 255) / 256, 256>>>();
    k_topk<<<N_TOT / 8, 256, smem_topk>>>();

    if (g_si.ok) {
        cudaStreamWaitEvent(0, g_si.evB, 0);   // join before edges
    } else {
        k_premm<<<(189 + 7) / 8, 256>>>(embed, Wrbf, W1);
        k_table<<<TAB / TROWS, 256>>>();
    }

    k_edges<<<N_TOT, 128>>>(b1);
    k_final<<<dim3(N_TOT / FBM, HID / FBN), 256>>>(embed, W2, b2, out);
}